// round 4
// baseline (speedup 1.0000x reference)
#include <cuda_runtime.h>
#include <stdint.h>

// SparseLaplacianBuilder: 2E=1.6M, d=4, n=50000.
// Output (float32): [ idx0[M] | idx1[M] | vals[M] ], M = 16n + 32E.
//
// 4-kernel pipeline:
//   1. k_edge: Gram upper-tri atomics + P = L^T R + deg-atomic-allocated item slots
//   2. k_scan_blocks / 3. k_scan_tot: output offsets from (1+deg)
//   4. k_expand: warp-per-node shfl rank-sort (+synthetic diag item) + x16 expansion
//
// Invariants across runs (graph replay): g_deg == 0 and g_diag == 0 on entry
// (zero at module load; restored by k_expand each run).

#define N_MAX   65536
#define E_MAX   1048576
#define K_SLOT  128
#define NB_MAX  64

__device__ float              g_diag[(size_t)N_MAX * 16];        // upper triangle; lower stays 0
__device__ float              g_P[(size_t)E_MAX * 16];
__device__ unsigned int       g_deg[N_MAX];
__device__ unsigned int       g_itemoff[N_MAX];                  // per-block-local exclusive scan
__device__ unsigned int       g_blktot[NB_MAX];
__device__ unsigned int       g_blkoff[NB_MAX];
__device__ unsigned long long g_items[(size_t)N_MAX * K_SLOT];   // strided slots, 64 MB

// key = (target << 22) | (class << 20) | e     class: 0=diag(synthetic), 1=ij, 2=ji

// ---------- 1. fused edge pass ----------
__global__ void k_edge(const float* __restrict__ maps, const int* __restrict__ ei,
                       int E, int twoE) {
    int e = blockIdx.x * blockDim.x + threadIdx.x;
    if (e >= E) return;

    float L[16], R[16];
    const float4* Lp = reinterpret_cast<const float4*>(maps + (size_t)e * 16);
    const float4* Rp = reinterpret_cast<const float4*>(maps + (size_t)(E + e) * 16);
#pragma unroll
    for (int k = 0; k < 4; k++) {
        float4 v = Lp[k];
        L[k*4+0] = v.x; L[k*4+1] = v.y; L[k*4+2] = v.z; L[k*4+3] = v.w;
        float4 w = Rp[k];
        R[k*4+0] = w.x; R[k*4+1] = w.y; R[k*4+2] = w.z; R[k*4+3] = w.w;
    }

    int row = ei[e];          // edge_index[0][e]
    int nR  = ei[E + e];      // edge_index[0][E+e]  (diag target for 2nd half)
    int col = ei[twoE + e];   // edge_index[1][e]

    float* dL = &g_diag[(size_t)row * 16];
    float* dR = &g_diag[(size_t)nR * 16];
#pragma unroll
    for (int a = 0; a < 4; a++) {
#pragma unroll
        for (int b = a; b < 4; b++) {                 // symmetric Gram: upper only
            float gl = 0.f, gr = 0.f;
#pragma unroll
            for (int k = 0; k < 4; k++) {
                gl += L[k*4+a] * L[k*4+b];
                gr += R[k*4+a] * R[k*4+b];
            }
            atomicAdd(dL + a*4 + b, gl);
            atomicAdd(dR + a*4 + b, gr);
        }
    }

    float Pv[16];
#pragma unroll
    for (int a = 0; a < 4; a++)
#pragma unroll
        for (int b = 0; b < 4; b++) {
            float p = 0.f;
#pragma unroll
            for (int k = 0; k < 4; k++) p += L[k*4+a] * R[k*4+b];
            Pv[a*4+b] = p;
        }
    float4* Pp = reinterpret_cast<float4*>(&g_P[(size_t)e * 16]);
#pragma unroll
    for (int k = 0; k < 4; k++)
        Pp[k] = make_float4(Pv[k*4], Pv[k*4+1], Pv[k*4+2], Pv[k*4+3]);

    // deg atomic doubles as slot allocator (order irrelevant — sort is total)
    unsigned c1 = atomicAdd(&g_deg[row], 1u);
    if (c1 < K_SLOT)
        g_items[(size_t)row * K_SLOT + c1] =
            (((unsigned long long)col) << 22) | (1ull << 20) | (unsigned)e;
    unsigned c2 = atomicAdd(&g_deg[col], 1u);
    if (c2 < K_SLOT)
        g_items[(size_t)col * K_SLOT + c2] =
            (((unsigned long long)row) << 22) | (2ull << 20) | (unsigned)e;
}

// ---------- 2. per-block shfl scan of (1+deg) ----------
__global__ void k_scan_blocks(int n) {
    __shared__ unsigned int wsum[32];
    int lane = (int)threadIdx.x & 31;
    int warp = (int)threadIdx.x >> 5;
    int i = blockIdx.x * 1024 + (int)threadIdx.x;
    unsigned x = (i < n) ? (1u + g_deg[i]) : 0u;
    unsigned v = x;
#pragma unroll
    for (int off = 1; off < 32; off <<= 1) {
        unsigned u = __shfl_up_sync(0xFFFFFFFFu, v, off);
        if (lane >= off) v += u;
    }
    if (lane == 31) wsum[warp] = v;
    __syncthreads();
    if (warp == 0) {
        unsigned w = wsum[lane];
#pragma unroll
        for (int off = 1; off < 32; off <<= 1) {
            unsigned u = __shfl_up_sync(0xFFFFFFFFu, w, off);
            if (lane >= off) w += u;
        }
        wsum[lane] = w;
    }
    __syncthreads();
    unsigned incl = v + (warp > 0 ? wsum[warp - 1] : 0u);
    if (i < n) g_itemoff[i] = incl - x;                 // block-local exclusive
    if (threadIdx.x == 1023) g_blktot[blockIdx.x] = incl;
}

// ---------- 3. scan of block totals ----------
__global__ void k_scan_tot(int nb) {
    __shared__ unsigned int s[NB_MAX];
    int t = (int)threadIdx.x;                           // blockDim = 64
    unsigned x = (t < nb) ? g_blktot[t] : 0u;
    s[t] = x;
    __syncthreads();
#pragma unroll
    for (int off = 1; off < NB_MAX; off <<= 1) {
        unsigned v = (t >= off) ? s[t - off] : 0u;
        __syncthreads();
        s[t] += v;
        __syncthreads();
    }
    if (t < nb) g_blkoff[t] = s[t] - x;                 // exclusive
}

// ---------- 4. warp-per-node sort + expansion ----------
__global__ void __launch_bounds__(256) k_expand(float* __restrict__ out, int n, size_t M) {
    __shared__ unsigned long long skeys[8][K_SLOT];
    int warp = (int)threadIdx.x >> 5;
    int lane = (int)threadIdx.x & 31;
    int wi   = blockIdx.x * 8 + warp;
    if (wi >= n) return;
    unsigned long long* sk = skeys[warp];

    unsigned dg = g_deg[wi];
    if (lane == 0) g_deg[wi] = 0u;                      // restore invariant (warp mem order: LDG before STG)
    if (dg > (unsigned)(K_SLOT - 1)) dg = K_SLOT - 1;
    int cnt = (int)dg + 1;
    size_t base = (size_t)wi * K_SLOT;
    unsigned long long diagkey = ((unsigned long long)wi) << 22;

    if (cnt <= 32) {
        unsigned long long k0 = (lane < (int)dg) ? g_items[base + lane]
                              : (lane == (int)dg ? diagkey : ~0ull);
        int r0 = 0;
#pragma unroll
        for (int s = 0; s < 32; s++) {
            unsigned long long o = __shfl_sync(0xFFFFFFFFu, k0, s);
            r0 += (int)(o < k0);
        }
        if (lane < cnt) sk[r0] = k0;
        __syncwarp();
    } else if (cnt <= 64) {
        int i1 = lane + 32;
        unsigned long long k0 = (lane < (int)dg) ? g_items[base + lane]
                              : (lane == (int)dg ? diagkey : ~0ull);
        unsigned long long k1 = (i1 < (int)dg) ? g_items[base + i1]
                              : (i1 == (int)dg ? diagkey : ~0ull);
        int r0 = 0, r1 = 0;
#pragma unroll
        for (int s = 0; s < 32; s++) {
            unsigned long long o0 = __shfl_sync(0xFFFFFFFFu, k0, s);
            unsigned long long o1 = __shfl_sync(0xFFFFFFFFu, k1, s);
            r0 += (int)(o0 < k0) + (int)(o1 < k0);
            r1 += (int)(o0 < k1) + (int)(o1 < k1);
        }
        if (lane < cnt) sk[r0] = k0;
        if (i1 < cnt)   sk[r1] = k1;
        __syncwarp();
    } else {
        // rare generic path (cnt <= 128): shared rank sort
        for (int i = lane; i < cnt; i += 32)
            sk[i] = (i < (int)dg) ? g_items[base + i] : diagkey;
        __syncwarp();
        unsigned long long kk[4]; int rr[4];
#pragma unroll
        for (int j = 0; j < 4; j++) {
            int i = lane + 32 * j;
            kk[j] = (i < cnt) ? sk[i] : ~0ull;
        }
        __syncwarp();
#pragma unroll
        for (int j = 0; j < 4; j++) {
            int i = lane + 32 * j;
            if (i < cnt) {
                int r = 0;
                for (int q = 0; q < cnt; q++) r += (int)(sk[q] < kk[j]);
                rr[j] = r;
            }
        }
        __syncwarp();
#pragma unroll
        for (int j = 0; j < 4; j++) {
            int i = lane + 32 * j;
            if (i < cnt) sk[rr[j]] = kk[j];
        }
        __syncwarp();
    }

    unsigned beg = g_itemoff[wi] + g_blkoff[wi >> 10];
    float* idx0 = out;
    float* idx1 = out + M;
    float* vals = out + 2 * M;
    size_t nodebase = (size_t)beg * 16;
    int fourcnt = cnt << 2;
    float fbase = (float)(wi << 2);

    for (int t = lane; t < cnt; t += 32) {
        unsigned long long key = sk[t];
        unsigned tgt = (unsigned)(key >> 22);
        unsigned cls = ((unsigned)(key >> 20)) & 3u;
        unsigned e   = (unsigned)key & 0xFFFFFu;

        int g0 = t; while (g0 > 0 && (unsigned)(sk[g0 - 1] >> 22) == tgt) g0--;
        int g1 = t; while (g1 + 1 < cnt && (unsigned)(sk[g1 + 1] >> 22) == tgt) g1++;
        int len = g1 - g0 + 1;

        float4 m0, m1, m2, m3;
        float4 V0, V1, V2, V3;
        if (cls == 0) {
            float4* s = reinterpret_cast<float4*>(&g_diag[(size_t)wi << 4]);
            m0 = s[0]; m1 = s[1]; m2 = s[2]; m3 = s[3];
            // symmetric reconstruction from upper triangle
            V0 = m0;
            V1 = make_float4(m0.y, m1.y, m1.z, m1.w);
            V2 = make_float4(m0.z, m1.z, m2.z, m2.w);
            V3 = make_float4(m0.w, m1.w, m2.w, m3.w);
            // restore zero-invariant (sole reader; loads above precede stores in warp order)
            float4 z = make_float4(0.f, 0.f, 0.f, 0.f);
            s[0] = z; s[1] = z; s[2] = z; s[3] = z;
        } else {
            const float4* s = reinterpret_cast<const float4*>(&g_P[(size_t)e << 4]);
            m0 = s[0]; m1 = s[1]; m2 = s[2]; m3 = s[3];
            if (cls == 1) {      // -P
                V0 = make_float4(-m0.x, -m0.y, -m0.z, -m0.w);
                V1 = make_float4(-m1.x, -m1.y, -m1.z, -m1.w);
                V2 = make_float4(-m2.x, -m2.y, -m2.z, -m2.w);
                V3 = make_float4(-m3.x, -m3.y, -m3.z, -m3.w);
            } else {             // -P^T
                V0 = make_float4(-m0.x, -m1.x, -m2.x, -m3.x);
                V1 = make_float4(-m0.y, -m1.y, -m2.y, -m3.y);
                V2 = make_float4(-m0.z, -m1.z, -m2.z, -m3.z);
                V3 = make_float4(-m0.w, -m1.w, -m2.w, -m3.w);
            }
        }

        float tj = (float)(tgt << 2);
        if (len == 1) {
            float4 j4 = make_float4(tj, tj + 1.f, tj + 2.f, tj + 3.f);
#pragma unroll
            for (int a = 0; a < 4; a++) {
                size_t pos = nodebase + (size_t)a * fourcnt + (t << 2);
                float fi = fbase + (float)a;
                *reinterpret_cast<float4*>(idx0 + pos) = make_float4(fi, fi, fi, fi);
                *reinterpret_cast<float4*>(idx1 + pos) = j4;
                float4 V = (a == 0) ? V0 : (a == 1) ? V1 : (a == 2) ? V2 : V3;
                *reinterpret_cast<float4*>(vals + pos) = V;
            }
        } else {
            int pbase = (g0 << 2) + (t - g0);
#pragma unroll
            for (int a = 0; a < 4; a++) {
                size_t rb = nodebase + (size_t)a * fourcnt + pbase;
                float fi = fbase + (float)a;
                float4 V = (a == 0) ? V0 : (a == 1) ? V1 : (a == 2) ? V2 : V3;
                float vb[4] = {V.x, V.y, V.z, V.w};
#pragma unroll
                for (int b = 0; b < 4; b++) {
                    size_t pos = rb + (size_t)b * len;
                    idx0[pos] = fi;
                    idx1[pos] = tj + (float)b;
                    vals[pos] = vb[b];
                }
            }
        }
    }
}

extern "C" void kernel_launch(void* const* d_in, const int* in_sizes, int n_in,
                              void* d_out, int out_size) {
    const float* maps = (const float*)d_in[0];
    const int*   ei   = (const int*)d_in[1];

    int twoE = in_sizes[0] / 16;
    int E    = twoE / 2;
    size_t M = (size_t)out_size / 3;
    int n    = (int)((M - (size_t)twoE * 16) / 16);
    int nb   = (n + 1023) / 1024;

    float* out = (float*)d_out;

    k_edge       <<<(E + 255) / 256, 256>>>(maps, ei, E, twoE);
    k_scan_blocks<<<nb, 1024>>>(n);
    k_scan_tot   <<<1, NB_MAX>>>(nb);
    k_expand     <<<(n + 7) / 8, 256>>>(out, n, M);
}

// round 5
// speedup vs baseline: 1.1308x; 1.1308x over previous
#include <cuda_runtime.h>
#include <stdint.h>

// SparseLaplacianBuilder: 2E=1.6M, d=4, n=50000.
// Output (float32): [ idx0[M] | idx1[M] | vals[M] ], M = 16n + 32E.
//
// 4-kernel pipeline:
//   1. k_edge: Gram upper-tri atomics + (-P, -P^T) stores + slab item scatter
//   2/3. scan of (1+deg) -> per-node output offsets
//   4. k_expand: warp-per-node shfl rank-sort, row-parallel x16 expansion
//
// Run-to-run invariants (graph replay): g_deg == 0, g_diag == 0 on entry
// (zeroed at module load; restored by k_expand each run).

#define N_MAX   65536
#define E_MAX   1048576
#define K_SLOT  128
#define NB_MAX  64

__device__ float              g_diag[(size_t)N_MAX * 16];        // upper triangle; lower stays 0
__device__ float              g_Pn [(size_t)E_MAX * 16];         // -P
__device__ float              g_PTn[(size_t)E_MAX * 16];         // -P^T
__device__ unsigned int       g_deg[N_MAX];
__device__ unsigned int       g_itemoff[N_MAX];
__device__ unsigned int       g_blktot[NB_MAX];
__device__ unsigned int       g_blkoff[NB_MAX];
__device__ unsigned long long g_items[(size_t)N_MAX * K_SLOT];

// key = (target << 22) | (class << 20) | e     class: 0=diag(synthetic), 1=ij, 2=ji

// ---------- 1. fused edge pass ----------
__global__ void k_edge(const float* __restrict__ maps, const int* __restrict__ ei,
                       int E, int twoE) {
    int e = blockIdx.x * blockDim.x + threadIdx.x;
    if (e >= E) return;

    float L[16], R[16];
    const float4* Lp = reinterpret_cast<const float4*>(maps + (size_t)e * 16);
    const float4* Rp = reinterpret_cast<const float4*>(maps + (size_t)(E + e) * 16);
#pragma unroll
    for (int k = 0; k < 4; k++) {
        float4 v = Lp[k];
        L[k*4+0] = v.x; L[k*4+1] = v.y; L[k*4+2] = v.z; L[k*4+3] = v.w;
        float4 w = Rp[k];
        R[k*4+0] = w.x; R[k*4+1] = w.y; R[k*4+2] = w.z; R[k*4+3] = w.w;
    }

    int row = ei[e];          // edge_index[0][e]
    int nR  = ei[E + e];      // edge_index[0][E+e]  (diag target of 2nd half)
    int col = ei[twoE + e];   // edge_index[1][e]

    float* dL = &g_diag[(size_t)row * 16];
    float* dR = &g_diag[(size_t)nR * 16];
#pragma unroll
    for (int a = 0; a < 4; a++) {
#pragma unroll
        for (int b = a; b < 4; b++) {                 // symmetric Gram: upper only
            float gl = 0.f, gr = 0.f;
#pragma unroll
            for (int k = 0; k < 4; k++) {
                gl += L[k*4+a] * L[k*4+b];
                gr += R[k*4+a] * R[k*4+b];
            }
            atomicAdd(dL + a*4 + b, gl);
            atomicAdd(dR + a*4 + b, gr);
        }
    }

    float Pv[16];
#pragma unroll
    for (int a = 0; a < 4; a++)
#pragma unroll
        for (int b = 0; b < 4; b++) {
            float p = 0.f;
#pragma unroll
            for (int k = 0; k < 4; k++) p += L[k*4+a] * R[k*4+b];
            Pv[a*4+b] = -p;                           // store negated
        }
    float4* Pp  = reinterpret_cast<float4*>(&g_Pn [(size_t)e * 16]);
    float4* PTp = reinterpret_cast<float4*>(&g_PTn[(size_t)e * 16]);
#pragma unroll
    for (int k = 0; k < 4; k++) {
        Pp[k]  = make_float4(Pv[k*4],   Pv[k*4+1], Pv[k*4+2],  Pv[k*4+3]);
        PTp[k] = make_float4(Pv[k],     Pv[4+k],   Pv[8+k],    Pv[12+k]);   // -P^T row k
    }

    unsigned c1 = atomicAdd(&g_deg[row], 1u);
    if (c1 < K_SLOT)
        g_items[(size_t)row * K_SLOT + c1] =
            (((unsigned long long)col) << 22) | (1ull << 20) | (unsigned)e;
    unsigned c2 = atomicAdd(&g_deg[col], 1u);
    if (c2 < K_SLOT)
        g_items[(size_t)col * K_SLOT + c2] =
            (((unsigned long long)row) << 22) | (2ull << 20) | (unsigned)e;
}

// ---------- 2. per-block shfl scan of (1+deg) ----------
__global__ void k_scan_blocks(int n) {
    __shared__ unsigned int wsum[32];
    int lane = (int)threadIdx.x & 31;
    int warp = (int)threadIdx.x >> 5;
    int i = blockIdx.x * 1024 + (int)threadIdx.x;
    unsigned x = (i < n) ? (1u + g_deg[i]) : 0u;
    unsigned v = x;
#pragma unroll
    for (int off = 1; off < 32; off <<= 1) {
        unsigned u = __shfl_up_sync(0xFFFFFFFFu, v, off);
        if (lane >= off) v += u;
    }
    if (lane == 31) wsum[warp] = v;
    __syncthreads();
    if (warp == 0) {
        unsigned w = wsum[lane];
#pragma unroll
        for (int off = 1; off < 32; off <<= 1) {
            unsigned u = __shfl_up_sync(0xFFFFFFFFu, w, off);
            if (lane >= off) w += u;
        }
        wsum[lane] = w;
    }
    __syncthreads();
    unsigned incl = v + (warp > 0 ? wsum[warp - 1] : 0u);
    if (i < n) g_itemoff[i] = incl - x;
    if (threadIdx.x == 1023) g_blktot[blockIdx.x] = incl;
}

// ---------- 3. scan of block totals ----------
__global__ void k_scan_tot(int nb) {
    __shared__ unsigned int s[NB_MAX];
    int t = (int)threadIdx.x;
    unsigned x = (t < nb) ? g_blktot[t] : 0u;
    s[t] = x;
    __syncthreads();
#pragma unroll
    for (int off = 1; off < NB_MAX; off <<= 1) {
        unsigned v = (t >= off) ? s[t - off] : 0u;
        __syncthreads();
        s[t] += v;
        __syncthreads();
    }
    if (t < nb) g_blkoff[t] = s[t] - x;
}

// ---------- 4. warp-per-node sort + row-parallel expansion ----------
__global__ void __launch_bounds__(256) k_expand(float* __restrict__ out, int n, size_t M) {
    __shared__ unsigned long long skeys[8][K_SLOT];
    __shared__ unsigned int       sruns[8][K_SLOT];
    int warp = (int)threadIdx.x >> 5;
    int lane = (int)threadIdx.x & 31;
    int wi   = blockIdx.x * 8 + warp;
    if (wi >= n) return;
    unsigned long long* sk = skeys[warp];
    unsigned int*       sr = sruns[warp];

    unsigned dg  = g_deg[wi];
    unsigned beg = g_itemoff[wi] + g_blkoff[wi >> 10];   // hoisted: overlap with sort
    if (lane == 0) g_deg[wi] = 0u;                       // restore invariant
    if (dg > (unsigned)(K_SLOT - 1)) dg = K_SLOT - 1;
    int cnt = (int)dg + 1;
    size_t base = (size_t)wi * K_SLOT;
    unsigned long long diagkey = ((unsigned long long)wi) << 22;

    // ---- rank sort into sk ----
    if (cnt <= 32) {
        unsigned long long k0 = (lane < (int)dg) ? g_items[base + lane]
                              : (lane == (int)dg ? diagkey : ~0ull);
        int r0 = 0;
#pragma unroll
        for (int s = 0; s < 32; s++) {
            unsigned long long o = __shfl_sync(0xFFFFFFFFu, k0, s);
            r0 += (int)(o < k0);
        }
        if (lane < cnt) sk[r0] = k0;
        __syncwarp();
    } else if (cnt <= 64) {
        int i1 = lane + 32;
        unsigned long long k0 = (lane < (int)dg) ? g_items[base + lane]
                              : (lane == (int)dg ? diagkey : ~0ull);
        unsigned long long k1 = (i1 < (int)dg) ? g_items[base + i1]
                              : (i1 == (int)dg ? diagkey : ~0ull);
        int r0 = 0, r1 = 0;
#pragma unroll
        for (int s = 0; s < 32; s++) {
            unsigned long long o0 = __shfl_sync(0xFFFFFFFFu, k0, s);
            unsigned long long o1 = __shfl_sync(0xFFFFFFFFu, k1, s);
            r0 += (int)(o0 < k0) + (int)(o1 < k0);
            r1 += (int)(o0 < k1) + (int)(o1 < k1);
        }
        if (lane < cnt) sk[r0] = k0;
        if (i1 < cnt)   sk[r1] = k1;
        __syncwarp();
    } else {                                   // rare: cnt in (64,128]
        for (int i = lane; i < cnt; i += 32)
            sk[i] = (i < (int)dg) ? g_items[base + i] : diagkey;
        __syncwarp();
        unsigned long long kk[4]; int rr[4];
#pragma unroll
        for (int j = 0; j < 4; j++) {
            int i = lane + 32 * j;
            kk[j] = (i < cnt) ? sk[i] : ~0ull;
        }
        __syncwarp();
#pragma unroll
        for (int j = 0; j < 4; j++) {
            int i = lane + 32 * j;
            if (i < cnt) {
                int r = 0;
                for (int q = 0; q < cnt; q++) r += (int)(sk[q] < kk[j]);
                rr[j] = r;
            }
        }
        __syncwarp();
#pragma unroll
        for (int j = 0; j < 4; j++) {
            int i = lane + 32 * j;
            if (i < cnt) sk[rr[j]] = kk[j];
        }
        __syncwarp();
    }

    // ---- per-item run info: pbase = 4*g0 + (t-g0), len (collisions are rare) ----
    for (int t = lane; t < cnt; t += 32) {
        unsigned tgt = (unsigned)(sk[t] >> 22);
        int g0 = t; while (g0 > 0 && (unsigned)(sk[g0 - 1] >> 22) == tgt) g0--;
        int g1 = t; while (g1 + 1 < cnt && (unsigned)(sk[g1 + 1] >> 22) == tgt) g1++;
        sr[t] = ((unsigned)((g0 << 2) + (t - g0)) << 8) | (unsigned)(g1 - g0 + 1);
    }
    __syncwarp();

    // ---- row-parallel expansion: lane owns (item t, row a) ----
    float* idx0 = out;
    float* idx1 = out + M;
    float* vals = out + 2 * M;
    size_t nodebase = (size_t)beg * 16;
    int fourcnt = cnt << 2;
    float fbase = (float)(wi << 2);

    for (int r = lane; r < fourcnt; r += 32) {
        int t = r >> 2, a = r & 3;
        unsigned long long key = sk[t];          // 4-lane broadcast LDS
        unsigned run = sr[t];
        unsigned tgt = (unsigned)(key >> 22);
        unsigned cls = ((unsigned)(key >> 20)) & 3u;
        unsigned e   = (unsigned)key & 0xFFFFFu;
        int pbase = (int)(run >> 8);
        int len   = (int)(run & 255u);

        float4 V;
        bool isdiag = (cls == 0);
        if (isdiag) {
            // row a of symmetric matrix from upper triangle
            const float* D = &g_diag[(size_t)wi << 4];
            float v0 = D[(a < 0 ? 0 : (0 < a ? 0*4 + a : a*4 + 0))];
            // explicit min/max indexing:
            int a0 = a; 
            v0   = D[(0 < a0 ? 0*4 + a0 : a0*4 + 0)];
            float v1 = D[(1 < a0 ? 1*4 + a0 : a0*4 + 1)];
            float v2 = D[(2 < a0 ? 2*4 + a0 : a0*4 + 2)];
            float v3 = D[(3 < a0 ? 3*4 + a0 : a0*4 + 3)];
            V = make_float4(v0, v1, v2, v3);
        } else {
            const float* src = (cls == 1) ? g_Pn : g_PTn;
            V = *reinterpret_cast<const float4*>(src + ((size_t)e << 4) + (a << 2));
        }

        float fi = fbase + (float)a;
        float tj = (float)(tgt << 2);
        size_t rowbase = nodebase + (size_t)a * fourcnt + pbase;

        if (len == 1) {
            *reinterpret_cast<float4*>(idx0 + rowbase) = make_float4(fi, fi, fi, fi);
            *reinterpret_cast<float4*>(idx1 + rowbase) = make_float4(tj, tj + 1.f, tj + 2.f, tj + 3.f);
            *reinterpret_cast<float4*>(vals + rowbase) = V;
        } else {
            float vb[4] = {V.x, V.y, V.z, V.w};
#pragma unroll
            for (int b = 0; b < 4; b++) {
                size_t pos = rowbase + (size_t)b * len;
                idx0[pos] = fi;
                idx1[pos] = tj + (float)b;
                vals[pos] = vb[b];
            }
        }

        if (isdiag) {
            // restore zero-invariant: issues after val STG (which consumed the loads)
            *reinterpret_cast<float4*>(&g_diag[((size_t)wi << 4) + (a << 2)]) =
                make_float4(0.f, 0.f, 0.f, 0.f);
        }
    }
}

extern "C" void kernel_launch(void* const* d_in, const int* in_sizes, int n_in,
                              void* d_out, int out_size) {
    const float* maps = (const float*)d_in[0];
    const int*   ei   = (const int*)d_in[1];

    int twoE = in_sizes[0] / 16;
    int E    = twoE / 2;
    size_t M = (size_t)out_size / 3;
    int n    = (int)((M - (size_t)twoE * 16) / 16);
    int nb   = (n + 1023) / 1024;

    float* out = (float*)d_out;

    k_edge       <<<(E + 255) / 256, 256>>>(maps, ei, E, twoE);
    k_scan_blocks<<<nb, 1024>>>(n);
    k_scan_tot   <<<1, NB_MAX>>>(nb);
    k_expand     <<<(n + 7) / 8, 256>>>(out, n, M);
}

// round 7
// speedup vs baseline: 1.3009x; 1.1504x over previous
#include <cuda_runtime.h>
#include <stdint.h>

// SparseLaplacianBuilder: 2E=1.6M, d=4, n=50000.
// Output (float32): [ idx0[M] | idx1[M] | vals[M] ], M = 16n + 32E.
//
// 4-kernel pipeline:
//   1. k_edge: full Gram via red.v4.f32 + (-P, -P^T) stores + slab item scatter
//   2/3. scan of (1+deg) -> per-node output offsets
//   4. k_expand: warp-per-node shfl rank-sort, row-parallel x16 expansion
//
// Run-to-run invariants (graph replay): g_deg == 0, g_diag == 0 on entry
// (zeroed at module load; restored by k_expand each run).

#define N_MAX   65536
#define E_MAX   1048576
#define K_SLOT  128
#define NB_MAX  64

__device__ float              g_diag[(size_t)N_MAX * 16];        // full symmetric matrix
__device__ float              g_Pn [(size_t)E_MAX * 16];         // -P
__device__ float              g_PTn[(size_t)E_MAX * 16];         // -P^T
__device__ unsigned int       g_deg[N_MAX];
__device__ unsigned int       g_itemoff[N_MAX];
__device__ unsigned int       g_blktot[NB_MAX];
__device__ unsigned int       g_blkoff[NB_MAX];
__device__ unsigned long long g_items[(size_t)N_MAX * K_SLOT];

// key = (target << 22) | (class << 20) | e     class: 0=diag(synthetic), 1=ij, 2=ji

__device__ __forceinline__ void red_row4(float* p, float x, float y, float z, float w) {
    asm volatile("red.global.add.v4.f32 [%0], {%1,%2,%3,%4};"
                 :: "l"(p), "f"(x), "f"(y), "f"(z), "f"(w) : "memory");
}

// ---------- 1. fused edge pass ----------
__global__ void k_edge(const float* __restrict__ maps, const int* __restrict__ ei,
                       int E, int twoE) {
    int e = blockIdx.x * blockDim.x + threadIdx.x;
    if (e >= E) return;

    float L[16], R[16];
    const float4* Lp = reinterpret_cast<const float4*>(maps + (size_t)e * 16);
    const float4* Rp = reinterpret_cast<const float4*>(maps + (size_t)(E + e) * 16);
#pragma unroll
    for (int k = 0; k < 4; k++) {
        float4 v = Lp[k];
        L[k*4+0] = v.x; L[k*4+1] = v.y; L[k*4+2] = v.z; L[k*4+3] = v.w;
        float4 w = Rp[k];
        R[k*4+0] = w.x; R[k*4+1] = w.y; R[k*4+2] = w.z; R[k*4+3] = w.w;
    }

    int row = ei[e];          // edge_index[0][e]
    int nR  = ei[E + e];      // edge_index[0][E+e]  (diag target of 2nd half)
    int col = ei[twoE + e];   // edge_index[1][e]

    // full Gram matrices (symmetric, computed fully — FMA is cheap)
    float GL[16], GR[16], Pv[16];
#pragma unroll
    for (int a = 0; a < 4; a++)
#pragma unroll
        for (int b = 0; b < 4; b++) {
            float gl = 0.f, gr = 0.f, p = 0.f;
#pragma unroll
            for (int k = 0; k < 4; k++) {
                gl += L[k*4+a] * L[k*4+b];
                gr += R[k*4+a] * R[k*4+b];
                p  += L[k*4+a] * R[k*4+b];
            }
            GL[a*4+b] = gl;
            GR[a*4+b] = gr;
            Pv[a*4+b] = -p;                           // store negated
        }

    float* dL = &g_diag[(size_t)row * 16];
    float* dR = &g_diag[(size_t)nR * 16];
#pragma unroll
    for (int a = 0; a < 4; a++) {
        red_row4(dL + (a << 2), GL[a*4], GL[a*4+1], GL[a*4+2], GL[a*4+3]);
        red_row4(dR + (a << 2), GR[a*4], GR[a*4+1], GR[a*4+2], GR[a*4+3]);
    }

    float4* Pp  = reinterpret_cast<float4*>(&g_Pn [(size_t)e * 16]);
    float4* PTp = reinterpret_cast<float4*>(&g_PTn[(size_t)e * 16]);
#pragma unroll
    for (int k = 0; k < 4; k++) {
        Pp[k]  = make_float4(Pv[k*4], Pv[k*4+1], Pv[k*4+2], Pv[k*4+3]);
        PTp[k] = make_float4(Pv[k],   Pv[4+k],   Pv[8+k],   Pv[12+k]);   // -P^T row k
    }

    unsigned c1 = atomicAdd(&g_deg[row], 1u);
    if (c1 < K_SLOT)
        g_items[(size_t)row * K_SLOT + c1] =
            (((unsigned long long)col) << 22) | (1ull << 20) | (unsigned)e;
    unsigned c2 = atomicAdd(&g_deg[col], 1u);
    if (c2 < K_SLOT)
        g_items[(size_t)col * K_SLOT + c2] =
            (((unsigned long long)row) << 22) | (2ull << 20) | (unsigned)e;
}

// ---------- 2. per-block shfl scan of (1+deg) ----------
__global__ void k_scan_blocks(int n) {
    __shared__ unsigned int wsum[32];
    int lane = (int)threadIdx.x & 31;
    int warp = (int)threadIdx.x >> 5;
    int i = blockIdx.x * 1024 + (int)threadIdx.x;
    unsigned x = (i < n) ? (1u + g_deg[i]) : 0u;
    unsigned v = x;
#pragma unroll
    for (int off = 1; off < 32; off <<= 1) {
        unsigned u = __shfl_up_sync(0xFFFFFFFFu, v, off);
        if (lane >= off) v += u;
    }
    if (lane == 31) wsum[warp] = v;
    __syncthreads();
    if (warp == 0) {
        unsigned w = wsum[lane];
#pragma unroll
        for (int off = 1; off < 32; off <<= 1) {
            unsigned u = __shfl_up_sync(0xFFFFFFFFu, w, off);
            if (lane >= off) w += u;
        }
        wsum[lane] = w;
    }
    __syncthreads();
    unsigned incl = v + (warp > 0 ? wsum[warp - 1] : 0u);
    if (i < n) g_itemoff[i] = incl - x;
    if (threadIdx.x == 1023) g_blktot[blockIdx.x] = incl;
}

// ---------- 3. scan of block totals ----------
__global__ void k_scan_tot(int nb) {
    __shared__ unsigned int s[NB_MAX];
    int t = (int)threadIdx.x;
    unsigned x = (t < nb) ? g_blktot[t] : 0u;
    s[t] = x;
    __syncthreads();
#pragma unroll
    for (int off = 1; off < NB_MAX; off <<= 1) {
        unsigned v = (t >= off) ? s[t - off] : 0u;
        __syncthreads();
        s[t] += v;
        __syncthreads();
    }
    if (t < nb) g_blkoff[t] = s[t] - x;
}

// ---------- 4. warp-per-node sort + row-parallel expansion ----------
__global__ void __launch_bounds__(256, 6) k_expand(float* __restrict__ out, int n, size_t M) {
    __shared__ unsigned long long skeys[8][K_SLOT];
    __shared__ unsigned int       sruns[8][K_SLOT];
    int warp = (int)threadIdx.x >> 5;
    int lane = (int)threadIdx.x & 31;
    int wi   = blockIdx.x * 8 + warp;
    if (wi >= n) return;
    unsigned long long* sk = skeys[warp];
    unsigned int*       sr = sruns[warp];

    unsigned dg  = g_deg[wi];
    unsigned beg = g_itemoff[wi] + g_blkoff[wi >> 10];
    if (lane == 0) g_deg[wi] = 0u;                       // restore invariant
    if (dg > (unsigned)(K_SLOT - 1)) dg = K_SLOT - 1;
    int cnt = (int)dg + 1;
    size_t base = (size_t)wi * K_SLOT;
    unsigned long long diagkey = ((unsigned long long)wi) << 22;

    // ---- rank sort into sk ----
    if (cnt <= 32) {
        unsigned long long k0 = (lane < (int)dg) ? g_items[base + lane]
                              : (lane == (int)dg ? diagkey : ~0ull);
        int r0 = 0;
#pragma unroll
        for (int s = 0; s < 32; s++) {
            unsigned long long o = __shfl_sync(0xFFFFFFFFu, k0, s);
            r0 += (int)(o < k0);
        }
        if (lane < cnt) sk[r0] = k0;
        __syncwarp();
    } else if (cnt <= 64) {
        int i1 = lane + 32;
        unsigned long long k0 = (lane < (int)dg) ? g_items[base + lane]
                              : (lane == (int)dg ? diagkey : ~0ull);
        unsigned long long k1 = (i1 < (int)dg) ? g_items[base + i1]
                              : (i1 == (int)dg ? diagkey : ~0ull);
        int r0 = 0, r1 = 0;
#pragma unroll
        for (int s = 0; s < 32; s++) {
            unsigned long long o0 = __shfl_sync(0xFFFFFFFFu, k0, s);
            unsigned long long o1 = __shfl_sync(0xFFFFFFFFu, k1, s);
            r0 += (int)(o0 < k0) + (int)(o1 < k0);
            r1 += (int)(o0 < k1) + (int)(o1 < k1);
        }
        if (lane < cnt) sk[r0] = k0;
        if (i1 < cnt)   sk[r1] = k1;
        __syncwarp();
    } else {                                   // rare: cnt in (64,128]
        for (int i = lane; i < cnt; i += 32)
            sk[i] = (i < (int)dg) ? g_items[base + i] : diagkey;
        __syncwarp();
        unsigned long long kk[4]; int rr[4];
#pragma unroll
        for (int j = 0; j < 4; j++) {
            int i = lane + 32 * j;
            kk[j] = (i < cnt) ? sk[i] : ~0ull;
        }
        __syncwarp();
#pragma unroll
        for (int j = 0; j < 4; j++) {
            int i = lane + 32 * j;
            if (i < cnt) {
                int r = 0;
                for (int q = 0; q < cnt; q++) r += (int)(sk[q] < kk[j]);
                rr[j] = r;
            }
        }
        __syncwarp();
#pragma unroll
        for (int j = 0; j < 4; j++) {
            int i = lane + 32 * j;
            if (i < cnt) sk[rr[j]] = kk[j];
        }
        __syncwarp();
    }

    // ---- per-item run info: pbase = 4*g0 + (t-g0), len ----
    for (int t = lane; t < cnt; t += 32) {
        unsigned tgt = (unsigned)(sk[t] >> 22);
        int g0 = t; while (g0 > 0 && (unsigned)(sk[g0 - 1] >> 22) == tgt) g0--;
        int g1 = t; while (g1 + 1 < cnt && (unsigned)(sk[g1 + 1] >> 22) == tgt) g1++;
        sr[t] = ((unsigned)((g0 << 2) + (t - g0)) << 8) | (unsigned)(g1 - g0 + 1);
    }
    __syncwarp();

    // ---- row-parallel expansion: lane owns (item t, row a) ----
    float* idx0 = out;
    float* idx1 = out + M;
    float* vals = out + 2 * M;
    size_t nodebase = (size_t)beg * 16;
    int fourcnt = cnt << 2;
    float fbase = (float)(wi << 2);

    for (int r = lane; r < fourcnt; r += 32) {
        int t = r >> 2, a = r & 3;
        unsigned long long key = sk[t];          // 4-lane broadcast LDS
        unsigned run = sr[t];
        unsigned tgt = (unsigned)(key >> 22);
        unsigned cls = ((unsigned)(key >> 20)) & 3u;
        unsigned e   = (unsigned)key & 0xFFFFFu;
        int pbase = (int)(run >> 8);
        int len   = (int)(run & 255u);

        bool isdiag = (cls == 0);
        const float* src = isdiag ? &g_diag[(size_t)wi << 4]
                         : (cls == 1 ? &g_Pn [(size_t)e << 4]
                                     : &g_PTn[(size_t)e << 4]);
        float4 V = *reinterpret_cast<const float4*>(src + (a << 2));

        float fi = fbase + (float)a;
        float tj = (float)(tgt << 2);
        size_t rowbase = nodebase + (size_t)a * fourcnt + pbase;

        if (len == 1) {
            *reinterpret_cast<float4*>(idx0 + rowbase) = make_float4(fi, fi, fi, fi);
            *reinterpret_cast<float4*>(idx1 + rowbase) = make_float4(tj, tj + 1.f, tj + 2.f, tj + 3.f);
            *reinterpret_cast<float4*>(vals + rowbase) = V;
        } else {
            float vb[4] = {V.x, V.y, V.z, V.w};
#pragma unroll
            for (int b = 0; b < 4; b++) {
                size_t pos = rowbase + (size_t)b * len;
                idx0[pos] = fi;
                idx1[pos] = tj + (float)b;
                vals[pos] = vb[b];
            }
        }

        if (isdiag) {
            // restore zero-invariant (store issues after the val consume above)
            *reinterpret_cast<float4*>(&g_diag[((size_t)wi << 4) + (a << 2)]) =
                make_float4(0.f, 0.f, 0.f, 0.f);
        }
    }
}

extern "C" void kernel_launch(void* const* d_in, const int* in_sizes, int n_in,
                              void* d_out, int out_size) {
    const float* maps = (const float*)d_in[0];
    const int*   ei   = (const int*)d_in[1];

    int twoE = in_sizes[0] / 16;
    int E    = twoE / 2;
    size_t M = (size_t)out_size / 3;
    int n    = (int)((M - (size_t)twoE * 16) / 16);
    int nb   = (n + 1023) / 1024;

    float* out = (float*)d_out;

    k_edge       <<<(E + 255) / 256, 256>>>(maps, ei, E, twoE);
    k_scan_blocks<<<nb, 1024>>>(n);
    k_scan_tot   <<<1, NB_MAX>>>(nb);
    k_expand     <<<(n + 7) / 8, 256>>>(out, n, M);
}

// round 11
// speedup vs baseline: 1.4452x; 1.1110x over previous
#include <cuda_runtime.h>
#include <stdint.h>

// SparseLaplacianBuilder: 2E=1.6M, d=4, n=50000.
// Output (float32): [ idx0[M] | idx1[M] | vals[M] ], M = 16n + 32E.
//
// 4-kernel pipeline:
//   1. k_edge: full Gram via red.v4.f32 + single -P store + slab item scatter
//   2/3. scan of (1+deg) -> per-node output offsets
//   4. k_expand: warp-per-node shfl rank-sort, row-parallel x16 expansion,
//      quad-shfl transpose for ji items, streaming (.cs) output stores.
//
// L2 strategy: only -P (51MB) + items (~19MB) + diag (3.2MB) are re-read by
// k_expand — all fit L2 (126MB); output stores use evict-first .cs so the
// 316MB stream does not evict them.
//
// Run-to-run invariants (graph replay): g_deg == 0, g_diag == 0 on entry
// (zeroed at module load; restored by k_expand each run).

#define N_MAX   65536
#define E_MAX   1048576
#define K_SLOT  128
#define NB_MAX  64

__device__ float              g_diag[(size_t)N_MAX * 16];        // full symmetric matrix
__device__ float              g_Pn [(size_t)E_MAX * 16];         // -P
__device__ unsigned int       g_deg[N_MAX];
__device__ unsigned int       g_itemoff[N_MAX];
__device__ unsigned int       g_blktot[NB_MAX];
__device__ unsigned int       g_blkoff[NB_MAX];
__device__ unsigned long long g_items[(size_t)N_MAX * K_SLOT];

// key = (target << 22) | (class << 20) | e     class: 0=diag(synthetic), 1=ij, 2=ji

__device__ __forceinline__ void red_row4(float* p, float x, float y, float z, float w) {
    asm volatile("red.global.add.v4.f32 [%0], {%1,%2,%3,%4};"
                 :: "l"(p), "f"(x), "f"(y), "f"(z), "f"(w) : "memory");
}

// ---------- 1. fused edge pass ----------
__global__ void k_edge(const float* __restrict__ maps, const int* __restrict__ ei,
                       int E, int twoE) {
    int e = blockIdx.x * blockDim.x + threadIdx.x;
    if (e >= E) return;

    float L[16], R[16];
    const float4* Lp = reinterpret_cast<const float4*>(maps + (size_t)e * 16);
    const float4* Rp = reinterpret_cast<const float4*>(maps + (size_t)(E + e) * 16);
#pragma unroll
    for (int k = 0; k < 4; k++) {
        float4 v = Lp[k];
        L[k*4+0] = v.x; L[k*4+1] = v.y; L[k*4+2] = v.z; L[k*4+3] = v.w;
        float4 w = Rp[k];
        R[k*4+0] = w.x; R[k*4+1] = w.y; R[k*4+2] = w.z; R[k*4+3] = w.w;
    }

    int row = ei[e];          // edge_index[0][e]
    int nR  = ei[E + e];      // edge_index[0][E+e]  (diag target of 2nd half)
    int col = ei[twoE + e];   // edge_index[1][e]

    float GL[16], GR[16], Pv[16];
#pragma unroll
    for (int a = 0; a < 4; a++)
#pragma unroll
        for (int b = 0; b < 4; b++) {
            float gl = 0.f, gr = 0.f, p = 0.f;
#pragma unroll
            for (int k = 0; k < 4; k++) {
                gl += L[k*4+a] * L[k*4+b];
                gr += R[k*4+a] * R[k*4+b];
                p  += L[k*4+a] * R[k*4+b];
            }
            GL[a*4+b] = gl;
            GR[a*4+b] = gr;
            Pv[a*4+b] = -p;                           // store negated
        }

    float* dL = &g_diag[(size_t)row * 16];
    float* dR = &g_diag[(size_t)nR * 16];
#pragma unroll
    for (int a = 0; a < 4; a++) {
        red_row4(dL + (a << 2), GL[a*4], GL[a*4+1], GL[a*4+2], GL[a*4+3]);
        red_row4(dR + (a << 2), GR[a*4], GR[a*4+1], GR[a*4+2], GR[a*4+3]);
    }

    float4* Pp = reinterpret_cast<float4*>(&g_Pn[(size_t)e * 16]);
#pragma unroll
    for (int k = 0; k < 4; k++)
        Pp[k] = make_float4(Pv[k*4], Pv[k*4+1], Pv[k*4+2], Pv[k*4+3]);

    unsigned c1 = atomicAdd(&g_deg[row], 1u);
    if (c1 < K_SLOT)
        g_items[(size_t)row * K_SLOT + c1] =
            (((unsigned long long)col) << 22) | (1ull << 20) | (unsigned)e;
    unsigned c2 = atomicAdd(&g_deg[col], 1u);
    if (c2 < K_SLOT)
        g_items[(size_t)col * K_SLOT + c2] =
            (((unsigned long long)row) << 22) | (2ull << 20) | (unsigned)e;
}

// ---------- 2. per-block shfl scan of (1+deg) ----------
__global__ void k_scan_blocks(int n) {
    __shared__ unsigned int wsum[32];
    int lane = (int)threadIdx.x & 31;
    int warp = (int)threadIdx.x >> 5;
    int i = blockIdx.x * 1024 + (int)threadIdx.x;
    unsigned x = (i < n) ? (1u + g_deg[i]) : 0u;
    unsigned v = x;
#pragma unroll
    for (int off = 1; off < 32; off <<= 1) {
        unsigned u = __shfl_up_sync(0xFFFFFFFFu, v, off);
        if (lane >= off) v += u;
    }
    if (lane == 31) wsum[warp] = v;
    __syncthreads();
    if (warp == 0) {
        unsigned w = wsum[lane];
#pragma unroll
        for (int off = 1; off < 32; off <<= 1) {
            unsigned u = __shfl_up_sync(0xFFFFFFFFu, w, off);
            if (lane >= off) w += u;
        }
        wsum[lane] = w;
    }
    __syncthreads();
    unsigned incl = v + (warp > 0 ? wsum[warp - 1] : 0u);
    if (i < n) g_itemoff[i] = incl - x;
    if (threadIdx.x == 1023) g_blktot[blockIdx.x] = incl;
}

// ---------- 3. scan of block totals ----------
__global__ void k_scan_tot(int nb) {
    __shared__ unsigned int s[NB_MAX];
    int t = (int)threadIdx.x;
    unsigned x = (t < nb) ? g_blktot[t] : 0u;
    s[t] = x;
    __syncthreads();
#pragma unroll
    for (int off = 1; off < NB_MAX; off <<= 1) {
        unsigned v = (t >= off) ? s[t - off] : 0u;
        __syncthreads();
        s[t] += v;
        __syncthreads();
    }
    if (t < nb) g_blkoff[t] = s[t] - x;
}

// ---------- 4. warp-per-node sort + row-parallel expansion ----------
__global__ void __launch_bounds__(256, 6) k_expand(float* __restrict__ out, int n, size_t M) {
    __shared__ unsigned long long skeys[8][K_SLOT];
    __shared__ unsigned int       sruns[8][K_SLOT];
    int warp = (int)threadIdx.x >> 5;
    int lane = (int)threadIdx.x & 31;
    int wi   = blockIdx.x * 8 + warp;
    if (wi >= n) return;
    unsigned long long* sk = skeys[warp];
    unsigned int*       sr = sruns[warp];

    unsigned dg  = g_deg[wi];
    unsigned beg = g_itemoff[wi] + g_blkoff[wi >> 10];
    if (lane == 0) g_deg[wi] = 0u;                       // restore invariant
    if (dg > (unsigned)(K_SLOT - 1)) dg = K_SLOT - 1;
    int cnt = (int)dg + 1;
    size_t base = (size_t)wi * K_SLOT;
    unsigned long long diagkey = ((unsigned long long)wi) << 22;

    // ---- rank sort into sk ----
    if (cnt <= 32) {
        unsigned long long k0 = (lane < (int)dg) ? g_items[base + lane]
                              : (lane == (int)dg ? diagkey : ~0ull);
        int r0 = 0;
#pragma unroll
        for (int s = 0; s < 32; s++) {
            unsigned long long o = __shfl_sync(0xFFFFFFFFu, k0, s);
            r0 += (int)(o < k0);
        }
        if (lane < cnt) sk[r0] = k0;
        __syncwarp();
    } else if (cnt <= 64) {
        int i1 = lane + 32;
        unsigned long long k0 = (lane < (int)dg) ? g_items[base + lane]
                              : (lane == (int)dg ? diagkey : ~0ull);
        unsigned long long k1 = (i1 < (int)dg) ? g_items[base + i1]
                              : (i1 == (int)dg ? diagkey : ~0ull);
        int r0 = 0, r1 = 0;
#pragma unroll
        for (int s = 0; s < 32; s++) {
            unsigned long long o0 = __shfl_sync(0xFFFFFFFFu, k0, s);
            unsigned long long o1 = __shfl_sync(0xFFFFFFFFu, k1, s);
            r0 += (int)(o0 < k0) + (int)(o1 < k0);
            r1 += (int)(o0 < k1) + (int)(o1 < k1);
        }
        if (lane < cnt) sk[r0] = k0;
        if (i1 < cnt)   sk[r1] = k1;
        __syncwarp();
    } else {                                   // rare: cnt in (64,128]
        for (int i = lane; i < cnt; i += 32)
            sk[i] = (i < (int)dg) ? g_items[base + i] : diagkey;
        __syncwarp();
        unsigned long long kk[4]; int rr[4];
#pragma unroll
        for (int j = 0; j < 4; j++) {
            int i = lane + 32 * j;
            kk[j] = (i < cnt) ? sk[i] : ~0ull;
        }
        __syncwarp();
#pragma unroll
        for (int j = 0; j < 4; j++) {
            int i = lane + 32 * j;
            if (i < cnt) {
                int r = 0;
                for (int q = 0; q < cnt; q++) r += (int)(sk[q] < kk[j]);
                rr[j] = r;
            }
        }
        __syncwarp();
#pragma unroll
        for (int j = 0; j < 4; j++) {
            int i = lane + 32 * j;
            if (i < cnt) sk[rr[j]] = kk[j];
        }
        __syncwarp();
    }

    // ---- per-item run info: pbase = 4*g0 + (t-g0), len ----
    for (int t = lane; t < cnt; t += 32) {
        unsigned tgt = (unsigned)(sk[t] >> 22);
        int g0 = t; while (g0 > 0 && (unsigned)(sk[g0 - 1] >> 22) == tgt) g0--;
        int g1 = t; while (g1 + 1 < cnt && (unsigned)(sk[g1 + 1] >> 22) == tgt) g1++;
        sr[t] = ((unsigned)((g0 << 2) + (t - g0)) << 8) | (unsigned)(g1 - g0 + 1);
    }
    __syncwarp();

    // ---- row-parallel expansion: lane owns (item t, row a); quad = item ----
    float* idx0 = out;
    float* idx1 = out + M;
    float* vals = out + 2 * M;
    size_t nodebase = (size_t)beg * 16;
    int fourcnt = cnt << 2;
    int padded  = (fourcnt + 31) & ~31;        // warp-uniform trip count (full-mask shfl)
    float fbase = (float)(wi << 2);

    for (int r = lane; r < padded; r += 32) {
        bool active = (r < fourcnt);
        int rr = active ? r : (fourcnt - 4 + (r & 3));   // clamp to last item, keep a = lane&3 shape
        int t = rr >> 2, a = rr & 3;
        unsigned long long key = sk[t];
        unsigned run = sr[t];
        unsigned tgt = (unsigned)(key >> 22);
        unsigned cls = ((unsigned)(key >> 20)) & 3u;
        unsigned e   = (unsigned)key & 0xFFFFFu;
        int pbase = (int)(run >> 8);
        int len   = (int)(run & 255u);

        bool isdiag = (cls == 0);
        const float* src = isdiag ? &g_diag[(size_t)wi << 4] : &g_Pn[(size_t)e << 4];
        float4 V = *reinterpret_cast<const float4*>(src + (a << 2));   // row a (L2-resident)

        // cls==2 (ji): need column a of -P = quad 4x4 transpose (cls is quad-uniform)
        {
            // stage 1: xor 2
            float s0 = (a & 2) ? V.x : V.z;
            float s1 = (a & 2) ? V.y : V.w;
            float r0 = __shfl_xor_sync(0xFFFFFFFFu, s0, 2);
            float r1 = __shfl_xor_sync(0xFFFFFFFFu, s1, 2);
            float4 T1 = (a & 2) ? make_float4(r0, r1, V.z, V.w)
                                : make_float4(V.x, V.y, r0, r1);
            // stage 2: xor 1
            float u0 = (a & 1) ? T1.x : T1.y;
            float u1 = (a & 1) ? T1.z : T1.w;
            float q0 = __shfl_xor_sync(0xFFFFFFFFu, u0, 1);
            float q1 = __shfl_xor_sync(0xFFFFFFFFu, u1, 1);
            float4 T2 = (a & 1) ? make_float4(q0, T1.y, q1, T1.w)
                                : make_float4(T1.x, q0, T1.z, q1);
            if (cls == 2) V = T2;
        }

        if (active) {
            float fi = fbase + (float)a;
            float tj = (float)(tgt << 2);
            size_t rowbase = nodebase + (size_t)a * fourcnt + pbase;

            if (len == 1) {
                __stcs(reinterpret_cast<float4*>(idx0 + rowbase), make_float4(fi, fi, fi, fi));
                __stcs(reinterpret_cast<float4*>(idx1 + rowbase), make_float4(tj, tj + 1.f, tj + 2.f, tj + 3.f));
                __stcs(reinterpret_cast<float4*>(vals + rowbase), V);
            } else {
                float vb[4] = {V.x, V.y, V.z, V.w};
#pragma unroll
                for (int b = 0; b < 4; b++) {
                    size_t pos = rowbase + (size_t)b * len;
                    __stcs(idx0 + pos, fi);
                    __stcs(idx1 + pos, tj + (float)b);
                    __stcs(vals + pos, vb[b]);
                }
            }

            if (isdiag) {
                // restore zero-invariant (store issues after the val consume above)
                *reinterpret_cast<float4*>(&g_diag[((size_t)wi << 4) + (a << 2)]) =
                    make_float4(0.f, 0.f, 0.f, 0.f);
            }
        }
    }
}

extern "C" void kernel_launch(void* const* d_in, const int* in_sizes, int n_in,
                              void* d_out, int out_size) {
    const float* maps = (const float*)d_in[0];
    const int*   ei   = (const int*)d_in[1];

    int twoE = in_sizes[0] / 16;
    int E    = twoE / 2;
    size_t M = (size_t)out_size / 3;
    int n    = (int)((M - (size_t)twoE * 16) / 16);
    int nb   = (n + 1023) / 1024;

    float* out = (float*)d_out;

    k_edge       <<<(E + 255) / 256, 256>>>(maps, ei, E, twoE);
    k_scan_blocks<<<nb, 1024>>>(n);
    k_scan_tot   <<<1, NB_MAX>>>(nb);
    k_expand     <<<(n + 7) / 8, 256>>>(out, n, M);
}